// round 14
// baseline (speedup 1.0000x reference)
#include <cuda_runtime.h>
#include <cuda_bf16.h>
#include <math.h>
#include <cstdint>

#define NB   32
#define TT   2048
#define DD   1024
#define NUB  8

// ---------------- device scratch (no allocs allowed) ----------------
__device__ float g_pq[NB * DD];
__device__ float g_wpart[NUB * NB * TT];
__device__ __nv_bfloat16 g_wk_hi[DD * DD];
__device__ __nv_bfloat16 g_wk_lo[DD * DD];
__device__ __nv_bfloat16 g_enc_hi[(size_t)NB * TT * DD];
__device__ __nv_bfloat16 g_enc_lo[(size_t)NB * TT * DD];
__device__ float g_ctxpart[8 * NB * DD];

// ---------------- helpers ----------------
__device__ __forceinline__ uint32_t smem_u32(const void* p) {
    uint32_t a;
    asm("{ .reg .u64 t; cvta.to.shared.u64 t, %1; cvt.u32.u64 %0, t; }" : "=r"(a) : "l"(p));
    return a;
}
__device__ __forceinline__ void ldsm4(uint32_t* r, uint32_t addr) {
    asm volatile("ldmatrix.sync.aligned.m8n8.x4.shared.b16 {%0,%1,%2,%3}, [%4];"
        : "=r"(r[0]), "=r"(r[1]), "=r"(r[2]), "=r"(r[3]) : "r"(addr));
}
__device__ __forceinline__ void mma16816(float* d, const uint32_t* a, const uint32_t* b) {
    asm volatile("mma.sync.aligned.m16n8k16.row.col.f32.bf16.bf16.f32 "
        "{%0,%1,%2,%3}, {%4,%5,%6,%7}, {%8,%9}, {%0,%1,%2,%3};"
        : "+f"(d[0]), "+f"(d[1]), "+f"(d[2]), "+f"(d[3])
        : "r"(a[0]), "r"(a[1]), "r"(a[2]), "r"(a[3]), "r"(b[0]), "r"(b[1]));
}
#define CP_ASYNC16(sts, g) \
    asm volatile("cp.async.cg.shared.global [%0], [%1], 16;" :: "r"(sts), "l"(g) : "memory")
#define CP_COMMIT() asm volatile("cp.async.commit_group;" ::: "memory")
#define CP_WAIT0()  asm volatile("cp.async.wait_group 0;" ::: "memory")

// ---------------- smem layout for k_weights_mma ----------------
// CTA tile 256(t) x 128(u), KC=32 per chunk. Row pitch 80B (64 data + 16 pad).
#define KC        32
#define ROWB      80
#define A_TILEB   (256 * ROWB)         // 20480
#define B_TILEB   (128 * ROWB)         // 10240
#define OFF_AH    0
#define OFF_AL    A_TILEB              // 20480
#define OFF_BH    (2 * A_TILEB)        // 40960
#define OFF_BL    (2 * A_TILEB + B_TILEB) // 51200
#define BUFB      (2 * A_TILEB + 2 * B_TILEB) // 61440
#define OFF_PQ    (2 * BUFB)           // 122880
#define OFF_V     (OFF_PQ + 512)
#define OFF_RED   (OFF_V + 512)        // 2 wn-groups x 256 rows
#define SMEMB     (OFF_RED + 2048)     // 125952

// ---------------------------------------------------------------------------
// K0a: split Wk into bf16 hi/lo
// ---------------------------------------------------------------------------
__global__ void k_split(const float* __restrict__ Wk)
{
    int i = (blockIdx.x * 256 + threadIdx.x) * 4;
    #pragma unroll
    for (int j = 0; j < 4; j++) {
        float x = Wk[i + j];
        __nv_bfloat16 h = __float2bfloat16(x);
        g_wk_hi[i + j] = h;
        g_wk_lo[i + j] = __float2bfloat16(x - __bfloat162float(h));
    }
}

// ---------------------------------------------------------------------------
// K0b: split enc into bf16 hi/lo (masked at 32-row granularity)
// ---------------------------------------------------------------------------
__global__ void k_enc_split(const float* __restrict__ enc, const int* __restrict__ lengths)
{
    int n = blockIdx.y;
    int t0 = blockIdx.x * 32;
    if (t0 >= lengths[n]) return;
    size_t base = ((size_t)n * TT + t0) * DD;
    #pragma unroll 4
    for (int i = threadIdx.x; i < 32 * DD / 4; i += 256) {
        float4 e = *(const float4*)(enc + base + (size_t)i * 4);
        __nv_bfloat16 h0 = __float2bfloat16(e.x), h1 = __float2bfloat16(e.y);
        __nv_bfloat16 h2 = __float2bfloat16(e.z), h3 = __float2bfloat16(e.w);
        uint2 hi = make_uint2(
            (uint32_t)__bfloat16_as_ushort(h0) | ((uint32_t)__bfloat16_as_ushort(h1) << 16),
            (uint32_t)__bfloat16_as_ushort(h2) | ((uint32_t)__bfloat16_as_ushort(h3) << 16));
        __nv_bfloat16 l0 = __float2bfloat16(e.x - __bfloat162float(h0));
        __nv_bfloat16 l1 = __float2bfloat16(e.y - __bfloat162float(h1));
        __nv_bfloat16 l2 = __float2bfloat16(e.z - __bfloat162float(h2));
        __nv_bfloat16 l3 = __float2bfloat16(e.w - __bfloat162float(h3));
        uint2 lo = make_uint2(
            (uint32_t)__bfloat16_as_ushort(l0) | ((uint32_t)__bfloat16_as_ushort(l1) << 16),
            (uint32_t)__bfloat16_as_ushort(l2) | ((uint32_t)__bfloat16_as_ushort(l3) << 16));
        *(uint2*)(g_enc_hi + base + (size_t)i * 4) = hi;
        *(uint2*)(g_enc_lo + base + (size_t)i * 4) = lo;
    }
}

// ---------------------------------------------------------------------------
// K1: pq[n,u] = q[n,:] . Wq[u,:]
// ---------------------------------------------------------------------------
__global__ void k_pq(const float* __restrict__ q, const float* __restrict__ Wq)
{
    int n = blockIdx.x;
    __shared__ float sq[DD];
    int tid = threadIdx.x;
    for (int i = tid; i < DD; i += 256) sq[i] = q[n * DD + i];
    __syncthreads();
    int warp = tid >> 5, lane = tid & 31;
    int ubase = blockIdx.y * 256 + warp * 32;
    for (int uu = 0; uu < 32; uu++) {
        int u = ubase + uu;
        const float* wr = Wq + (size_t)u * DD;
        float s = 0.f;
        #pragma unroll 8
        for (int m = 0; m < 32; m++) s = fmaf(sq[lane + 32 * m], wr[lane + 32 * m], s);
        #pragma unroll
        for (int off = 16; off; off >>= 1) s += __shfl_xor_sync(0xffffffffu, s, off);
        if (lane == 0) g_pq[n * DD + u] = s;
    }
}

// ---------------------------------------------------------------------------
// K2: split-bf16 HMMA GEMM, CTA 256x128, warp tile 64x64 (8 warps, 4m x 2n)
// grid (TT/256=8, NB, NUB), 256 threads
// ---------------------------------------------------------------------------
__global__ __launch_bounds__(256, 1)
void k_weights_mma(const float* __restrict__ v, const int* __restrict__ lengths)
{
    int tb = blockIdx.x, n = blockIdx.y, ub = blockIdx.z;
    int len = lengths[n];
    int t0 = tb * 256;
    if (t0 >= len) return;

    extern __shared__ char smem[];
    uint32_t sb = smem_u32(smem);
    float* spq  = (float*)(smem + OFF_PQ);
    float* sv   = (float*)(smem + OFF_V);
    float* sred = (float*)(smem + OFF_RED);

    int tid = threadIdx.x, lane = tid & 31, wid = tid >> 5;
    int wm = wid >> 1, wn = wid & 1;    // 4 (m) x 2 (n), warp tile 64x64

    if (tid < 128) {
        spq[tid] = g_pq[n * DD + ub * 128 + tid];
        sv[tid]  = v[ub * 128 + tid];
    }

    const __nv_bfloat16* ahg = g_enc_hi + ((size_t)n * TT + t0) * DD;
    const __nv_bfloat16* alg = g_enc_lo + ((size_t)n * TT + t0) * DD;
    const __nv_bfloat16* bhg = g_wk_hi + (size_t)ub * 128 * DD;
    const __nv_bfloat16* blg = g_wk_lo + (size_t)ub * 128 * DD;

    float acc[4][8][4];
    #pragma unroll
    for (int mi = 0; mi < 4; mi++)
        #pragma unroll
        for (int nj = 0; nj < 8; nj++)
            #pragma unroll
            for (int c = 0; c < 4; c++) acc[mi][nj][c] = 0.f;

    // ---- prologue: stage chunk 0 into buffer 0
    {
        // A: 2 arrays x 1024 units (row=u>>2, su=u&3), 4 units/thread each
        #pragma unroll
        for (int it = 0; it < 4; it++) {
            int u = tid + it * 256, row = u >> 2, su = u & 3;
            size_t go = (size_t)row * DD + su * 8;
            uint32_t so = (uint32_t)(row * ROWB + su * 16);
            CP_ASYNC16(sb + OFF_AH + so, ahg + go);
            CP_ASYNC16(sb + OFF_AL + so, alg + go);
        }
        // B: 2 arrays x 512 units, 2 units/thread each
        #pragma unroll
        for (int it = 0; it < 2; it++) {
            int u = tid + it * 256, row = u >> 2, su = u & 3;
            size_t go = (size_t)row * DD + su * 8;
            uint32_t so = (uint32_t)(row * ROWB + su * 16);
            CP_ASYNC16(sb + OFF_BH + so, bhg + go);
            CP_ASYNC16(sb + OFF_BL + so, blg + go);
        }
        CP_COMMIT(); CP_WAIT0();
    }
    __syncthreads();

    for (int c = 0; c < 32; c++) {
        uint32_t cur = sb + (uint32_t)(c & 1) * BUFB;
        uint32_t nxt = sb + (uint32_t)((c + 1) & 1) * BUFB;
        int kcn = (c + 1) * KC;
        bool pf = (c < 31);

        if (pf) {
            #pragma unroll
            for (int it = 0; it < 4; it++) {
                int u = tid + it * 256, row = u >> 2, su = u & 3;
                size_t go = (size_t)row * DD + kcn + su * 8;
                uint32_t so = (uint32_t)(row * ROWB + su * 16);
                CP_ASYNC16(nxt + OFF_AH + so, ahg + go);
                CP_ASYNC16(nxt + OFF_AL + so, alg + go);
            }
            #pragma unroll
            for (int it = 0; it < 2; it++) {
                int u = tid + it * 256, row = u >> 2, su = u & 3;
                size_t go = (size_t)row * DD + kcn + su * 8;
                uint32_t so = (uint32_t)(row * ROWB + su * 16);
                CP_ASYNC16(nxt + OFF_BH + so, bhg + go);
                CP_ASYNC16(nxt + OFF_BL + so, blg + go);
            }
            CP_COMMIT();
        }

        // ---- consume current buffer: 2 k-steps of 16
        #pragma unroll
        for (int ks = 0; ks < 2; ks++) {
            uint32_t bH[8][2], bL[8][2];
            #pragma unroll
            for (int p = 0; p < 4; p++) {
                int row = wn * 64 + p * 16 + (lane & 7) + ((lane >> 4) << 3);
                uint32_t byte = (uint32_t)(row * ROWB + ks * 32 + (((lane >> 3) & 1) << 4));
                uint32_t r[4];
                ldsm4(r, cur + OFF_BH + byte);
                bH[2 * p][0] = r[0]; bH[2 * p][1] = r[1];
                bH[2 * p + 1][0] = r[2]; bH[2 * p + 1][1] = r[3];
                ldsm4(r, cur + OFF_BL + byte);
                bL[2 * p][0] = r[0]; bL[2 * p][1] = r[1];
                bL[2 * p + 1][0] = r[2]; bL[2 * p + 1][1] = r[3];
            }
            #pragma unroll
            for (int mi = 0; mi < 4; mi++) {
                uint32_t aH[4], aL[4];
                int row = wm * 64 + mi * 16 + (lane & 15);
                uint32_t byte = (uint32_t)(row * ROWB + ks * 32 + ((lane >> 4) << 4));
                ldsm4(aH, cur + OFF_AH + byte);
                ldsm4(aL, cur + OFF_AL + byte);
                #pragma unroll
                for (int nj = 0; nj < 8; nj++) {
                    mma16816(acc[mi][nj], aH, bH[nj]);
                    mma16816(acc[mi][nj], aH, bL[nj]);
                    mma16816(acc[mi][nj], aL, bH[nj]);
                }
            }
        }

        if (pf) CP_WAIT0();
        __syncthreads();
    }

    // ---- epilogue: tanh(acc + pq)*v, reduce over u
    float rs[4][2];
    #pragma unroll
    for (int mi = 0; mi < 4; mi++) { rs[mi][0] = 0.f; rs[mi][1] = 0.f; }
    #pragma unroll
    for (int mi = 0; mi < 4; mi++)
        #pragma unroll
        for (int nj = 0; nj < 8; nj++) {
            int cu = wn * 64 + nj * 8 + (lane & 3) * 2;
            float p0 = spq[cu], p1 = spq[cu + 1];
            float v0 = sv[cu],  v1 = sv[cu + 1];
            rs[mi][0] += tanhf(acc[mi][nj][0] + p0) * v0 + tanhf(acc[mi][nj][1] + p1) * v1;
            rs[mi][1] += tanhf(acc[mi][nj][2] + p0) * v0 + tanhf(acc[mi][nj][3] + p1) * v1;
        }
    #pragma unroll
    for (int off = 1; off <= 2; off <<= 1)
        #pragma unroll
        for (int mi = 0; mi < 4; mi++) {
            rs[mi][0] += __shfl_xor_sync(0xffffffffu, rs[mi][0], off);
            rs[mi][1] += __shfl_xor_sync(0xffffffffu, rs[mi][1], off);
        }
    if ((lane & 3) == 0) {
        int tg = lane >> 2;
        #pragma unroll
        for (int mi = 0; mi < 4; mi++) {
            int r0 = wm * 64 + mi * 16 + tg;
            sred[wn * 256 + r0]     = rs[mi][0];
            sred[wn * 256 + r0 + 8] = rs[mi][1];
        }
    }
    __syncthreads();
    {
        float part = sred[tid] + sred[256 + tid];
        g_wpart[((size_t)ub * NB + n) * TT + t0 + tid] = part;
    }
}

// ---------------------------------------------------------------------------
// K3: sum u-block partials, mask, stable softmax -> alignments
// ---------------------------------------------------------------------------
__global__ void k_softmax(const int* __restrict__ lengths, float* __restrict__ align)
{
    int n = blockIdx.x, tid = threadIdx.x;
    int len = lengths[n];
    int warp = tid >> 5, lane = tid & 31;
    __shared__ float sredb[8];

    float w[8];
    float mx = -INFINITY;
    #pragma unroll
    for (int r = 0; r < 8; r++) {
        int t = r * 256 + tid;
        float s;
        if (t < len) {
            s = 0.f;
            #pragma unroll
            for (int p = 0; p < NUB; p++)
                s += g_wpart[((size_t)p * NB + n) * TT + t];
        } else {
            s = -INFINITY;
        }
        w[r] = s;
        mx = fmaxf(mx, s);
    }
    #pragma unroll
    for (int off = 16; off; off >>= 1) mx = fmaxf(mx, __shfl_xor_sync(0xffffffffu, mx, off));
    if (lane == 0) sredb[warp] = mx;
    __syncthreads();
    if (tid < 32) {
        float m2 = (tid < 8) ? sredb[tid] : -INFINITY;
        #pragma unroll
        for (int off = 4; off; off >>= 1) m2 = fmaxf(m2, __shfl_xor_sync(0xffffffffu, m2, off));
        if (tid == 0) sredb[0] = m2;
    }
    __syncthreads();
    mx = sredb[0];

    float sum = 0.f;
    #pragma unroll
    for (int r = 0; r < 8; r++) { float e = expf(w[r] - mx); w[r] = e; sum += e; }
    __syncthreads();
    #pragma unroll
    for (int off = 16; off; off >>= 1) sum += __shfl_xor_sync(0xffffffffu, sum, off);
    if (lane == 0) sredb[warp] = sum;
    __syncthreads();
    if (tid < 32) {
        float s2 = (tid < 8) ? sredb[tid] : 0.f;
        #pragma unroll
        for (int off = 4; off; off >>= 1) s2 += __shfl_xor_sync(0xffffffffu, s2, off);
        if (tid == 0) sredb[0] = s2;
    }
    __syncthreads();
    float inv = 1.0f / sredb[0];
    #pragma unroll
    for (int r = 0; r < 8; r++) {
        int t = r * 256 + tid;
        align[(size_t)n * TT + t] = w[r] * inv;
    }
}

// ---------------------------------------------------------------------------
// K4: context partials, 4 independent accumulators for ILP/MLP
// ---------------------------------------------------------------------------
__global__ void k_ctx(const float* __restrict__ enc, const float* __restrict__ align,
                      const int* __restrict__ lengths)
{
    int ec = blockIdx.x, n = blockIdx.y, ts = blockIdx.z;
    int tid = threadIdx.x;
    int len = lengths[n];
    int tbeg = ts * 256;
    int tend = min(len, tbeg + 256);

    __shared__ float sa[256];
    {
        int t = tbeg + tid;
        sa[tid] = (t < tend) ? align[(size_t)n * TT + t] : 0.f;
    }
    __syncthreads();

    int e = ec * 256 + tid;
    const float* eb = enc + (size_t)n * TT * DD + e + (size_t)tbeg * DD;
    int cnt = tend - tbeg;

    float a0 = 0.f, a1 = 0.f, a2 = 0.f, a3 = 0.f;
    int i = 0;
    int cnt4 = cnt & ~3;
    #pragma unroll 2
    for (; i < cnt4; i += 4) {
        a0 = fmaf(sa[i],     eb[(size_t)i * DD],       a0);
        a1 = fmaf(sa[i + 1], eb[(size_t)(i + 1) * DD], a1);
        a2 = fmaf(sa[i + 2], eb[(size_t)(i + 2) * DD], a2);
        a3 = fmaf(sa[i + 3], eb[(size_t)(i + 3) * DD], a3);
    }
    for (; i < cnt; i++)
        a0 = fmaf(sa[i], eb[(size_t)i * DD], a0);
    g_ctxpart[((size_t)ts * NB + n) * DD + e] = (a0 + a1) + (a2 + a3);
}

__global__ void k_comb(float* __restrict__ ctx)
{
    int idx = blockIdx.x * 256 + threadIdx.x;
    float s = 0.f;
    #pragma unroll
    for (int p = 0; p < 8; p++) s += g_ctxpart[(size_t)p * NB * DD + idx];
    ctx[idx] = s;
}

// ---------------------------------------------------------------------------
extern "C" void kernel_launch(void* const* d_in, const int* in_sizes, int n_in,
                              void* d_out, int out_size)
{
    const float* q   = (const float*)d_in[0];
    const float* enc = (const float*)d_in[1];
    const int*   len = (const int*)  d_in[2];
    const float* v   = (const float*)d_in[3];
    const float* Wq  = (const float*)d_in[4];
    const float* Wk  = (const float*)d_in[5];

    float* out       = (float*)d_out;
    float* out_ctx   = out;
    float* out_align = out + NB * DD;

    cudaFuncSetAttribute(k_weights_mma, cudaFuncAttributeMaxDynamicSharedMemorySize, SMEMB);

    k_split      <<<DD * DD / 1024, 256>>>(Wk);
    k_enc_split  <<<dim3(TT / 32, NB), 256>>>(enc, len);
    k_pq         <<<dim3(NB, 4), 256>>>(q, Wq);
    k_weights_mma<<<dim3(TT / 256, NB, NUB), 256, SMEMB>>>(v, len);
    k_softmax    <<<NB, 256>>>(len, out_align);
    k_ctx        <<<dim3(4, NB, 8), 256>>>(enc, out_align, len);
    k_comb       <<<NB * DD / 256, 256>>>(out_ctx);
}